// round 9
// baseline (speedup 1.0000x reference)
#include <cuda_runtime.h>
#include <cuda_fp16.h>

#define RES 256
#define NA  180
#define NB  4
#define PW  257            // x0p in [0,256]
#define PH  257            // y0p in [0,256]
#define NPIX (PH*PW)
#define NOUT (NB*NA*RES)

// Corner-packed fp16 images, batches interleaved INSIDE each half2 so the
// bilerp runs as half2 SIMD over batch pairs. 32 bytes per padded pixel:
//   w0 = h2(b0.v00, b1.v00)   w4 = h2(b2.v00, b3.v00)
//   w1 = h2(b0.v01, b1.v01)   w5 = h2(b2.v01, b3.v01)
//   w2 = h2(b0.v10, b1.v10)   w6 = h2(b2.v10, b3.v10)
//   w3 = h2(b0.v11, b1.v11)   w7 = h2(b2.v11, b3.v11)
// vXY = img[y0+X][x0+Y], OOB -> 0 (zero border = reference's validity mask).
struct __align__(32) Px { uint4 a, b; };
__device__ Px g_P[NPIX];

__device__ __forceinline__ unsigned pack2(float a, float b) {
    __half2 h = __floats2half2_rn(a, b);
    return *reinterpret_cast<unsigned*>(&h);
}
__device__ __forceinline__ __half2 as_h2(unsigned u) {
    return *reinterpret_cast<__half2*>(&u);
}

// 256-bit global load (sm_100+).
__device__ __forceinline__ void ldg256(const Px* p, uint4& a, uint4& b) {
    asm volatile("ld.global.nc.v8.u32 {%0,%1,%2,%3,%4,%5,%6,%7}, [%8];"
                 : "=r"(a.x), "=r"(a.y), "=r"(a.z), "=r"(a.w),
                   "=r"(b.x), "=r"(b.y), "=r"(b.z), "=r"(b.w)
                 : "l"(p));
}
// Register barrier: placed AFTER the second volatile load, ties the first
// load's output regs so their consumption cannot be hoisted between the two
// loads. Guarantees both loads are issued back-to-back (MLP >= 2).
__device__ __forceinline__ void regbar(uint4& a, uint4& b) {
    asm volatile("" : "+r"(a.x), "+r"(a.y), "+r"(a.z), "+r"(a.w),
                      "+r"(b.x), "+r"(b.y), "+r"(b.z), "+r"(b.w));
}

// Prep: build corner-packed array AND zero the output (radon adds atomically).
__global__ __launch_bounds__(256) void prep_kernel(const float* __restrict__ imgs,
                                                   float* __restrict__ out)
{
    int idx = blockIdx.x * blockDim.x + threadIdx.x;
    if (idx < NOUT) out[idx] = 0.0f;
    if (idx >= NPIX) return;
    const int xp = idx % PW;
    const int yp = idx / PW;
    const int yt = yp - 1, yb = yp;
    const int xl = xp - 1, xr = xp;

    float v[NB][4];
    #pragma unroll
    for (int b = 0; b < NB; ++b) {
        const float* im = imgs + (size_t)b * RES * RES;
        const bool vt = ((unsigned)yt < RES), vb = ((unsigned)yb < RES);
        const bool vl = ((unsigned)xl < RES), vr = ((unsigned)xr < RES);
        v[b][0] = (vt && vl) ? im[yt * RES + xl] : 0.0f;   // v00
        v[b][1] = (vt && vr) ? im[yt * RES + xr] : 0.0f;   // v01
        v[b][2] = (vb && vl) ? im[yb * RES + xl] : 0.0f;   // v10
        v[b][3] = (vb && vr) ? im[yb * RES + xr] : 0.0f;   // v11
    }
    Px px;
    px.a.x = pack2(v[0][0], v[1][0]);   // v00 of b0,b1
    px.a.y = pack2(v[0][1], v[1][1]);   // v01
    px.a.z = pack2(v[0][2], v[1][2]);   // v10
    px.a.w = pack2(v[0][3], v[1][3]);   // v11
    px.b.x = pack2(v[2][0], v[3][0]);
    px.b.y = pack2(v[2][1], v[3][1]);
    px.b.z = pack2(v[2][2], v[3][2]);
    px.b.w = pack2(v[2][3], v[3][3]);
    g_P[idx] = px;
}

// Bilerp for a batch pair, fully in half2 SIMD; returns float2 sample.
__device__ __forceinline__ float2 bilerp_h2(const uint4& q,
                                            __half2 wx2, __half2 wy2)
{
    const __half2 v00 = as_h2(q.x), v01 = as_h2(q.y);
    const __half2 v10 = as_h2(q.z), v11 = as_h2(q.w);
    const __half2 top = __hfma2(wx2, __hsub2(v01, v00), v00);
    const __half2 bot = __hfma2(wx2, __hsub2(v11, v10), v10);
    const __half2 smp = __hfma2(wy2, __hsub2(bot, top), top);
    return __half22float2(smp);
}

__device__ __forceinline__ void sample_acc(float fx, float fy,
                                           const uint4& qa, const uint4& qb,
                                           int x0, int y0,
                                           float& a0, float& a1,
                                           float& a2, float& a3)
{
    const float wx = fx - (float)x0;
    const float wy = fy - (float)y0;
    const __half2 wx2 = __floats2half2_rn(wx, wx);
    const __half2 wy2 = __floats2half2_rn(wy, wy);
    const float2 s01 = bilerp_h2(qa, wx2, wy2);
    const float2 s23 = bilerp_h2(qb, wx2, wy2);
    a0 += s01.x;  a1 += s01.y;
    a2 += s23.x;  a3 += s23.y;
}

// Accumulate NITER samples starting at (gx,gy), advancing (sxs,sys) per iter.
// Chunked by 2 with forced back-to-back loads.
template<int NITER>
__device__ __forceinline__ void accumulate(float gx, float gy,
                                           float sxs, float sys,
                                           float& a0, float& a1,
                                           float& a2, float& a3)
{
    #pragma unroll 4
    for (int i = 0; i < NITER / 2; ++i) {
        const float fx0 = gx,       fy0 = gy;
        const float fx1 = gx + sxs, fy1 = gy + sys;
        const int x00 = __float2int_rd(fx0), y00 = __float2int_rd(fy0);
        const int x01 = __float2int_rd(fx1), y01 = __float2int_rd(fy1);
        uint4 qa0, qb0, qa1, qb1;
        ldg256(g_P + (y00 * PW + x00), qa0, qb0);
        ldg256(g_P + (y01 * PW + x01), qa1, qb1);
        regbar(qa0, qb0);
        sample_acc(fx0, fy0, qa0, qb0, x00, y00, a0, a1, a2, a3);
        sample_acc(fx1, fy1, qa1, qb1, x01, y01, a0, a1, a2, a3);
        gx += 2.0f * sxs;
        gy += 2.0f * sys;
    }
}

// Block = 128 threads (4 warps). Grid: (angle, ray_group 0..7, t_half 0..1).
// Each block: 32 rays x 128 t-steps. Warp tile is angle-adaptive:
//   |cos| >= |sin| ("flat"):  8 rays x 4 t-phases, 32 iters.
//   |sin| >  |cos| ("steep"): 4 rays x 8 t-phases, 2 passes x 16 iters.
__global__ __launch_bounds__(128) void radon_kernel(
    const float* __restrict__ angles,
    const float* __restrict__ rays,
    float* __restrict__ out)
{
    const int tid  = threadIdx.x;
    const int lane = tid & 31;
    const int warp = tid >> 5;        // 0..3
    const int a    = blockIdx.x;      // angle
    const int rg   = blockIdx.y;      // ray group 0..7
    const int th   = blockIdx.z;      // t half 0..1

    float s, c;
    sincosf(__ldg(angles + a), &s, &c);
    const float inv_n = 1.0f / RES;
    const bool steep = fabsf(s) > fabsf(c);

    if (!steep) {
        const int r_i = lane & 7;     // 8 rays
        const int t_i = lane >> 3;    // 4 phases
        const int ray = rg * 32 + warp * 8 + r_i;

        const float4 r4 = __ldg(reinterpret_cast<const float4*>(rays) + ray);
        const float rsx = r4.x * c - r4.y * s;
        const float rsy = r4.x * s + r4.y * c;
        const float dx  = (r4.z * c - r4.w * s) - rsx;
        const float dy  = (r4.z * s + r4.w * c) - rsy;
        const float t0  = (float)(th * 128 + t_i) + 0.5f;
        const float gx  = rsx + 128.5f + dx * inv_n * t0;
        const float gy  = rsy + 128.5f + dy * inv_n * t0;

        float a0 = 0.f, a1 = 0.f, a2 = 0.f, a3 = 0.f;
        accumulate<32>(gx, gy, dx * inv_n * 4.0f, dy * inv_n * 4.0f,
                       a0, a1, a2, a3);

        a0 += __shfl_xor_sync(0xFFFFFFFFu, a0, 8);
        a0 += __shfl_xor_sync(0xFFFFFFFFu, a0, 16);
        a1 += __shfl_xor_sync(0xFFFFFFFFu, a1, 8);
        a1 += __shfl_xor_sync(0xFFFFFFFFu, a1, 16);
        a2 += __shfl_xor_sync(0xFFFFFFFFu, a2, 8);
        a2 += __shfl_xor_sync(0xFFFFFFFFu, a2, 16);
        a3 += __shfl_xor_sync(0xFFFFFFFFu, a3, 8);
        a3 += __shfl_xor_sync(0xFFFFFFFFu, a3, 16);

        if (t_i == 0) {
            const float step = (r4.w - r4.y) * inv_n;
            const int base = a * RES + ray;
            atomicAdd(out + 0 * NA * RES + base, a0 * step);
            atomicAdd(out + 1 * NA * RES + base, a1 * step);
            atomicAdd(out + 2 * NA * RES + base, a2 * step);
            atomicAdd(out + 3 * NA * RES + base, a3 * step);
        }
    } else {
        const int r_i = lane & 3;     // 4 rays
        const int t_i = lane >> 2;    // 8 phases

        #pragma unroll
        for (int p = 0; p < 2; ++p) {
            const int ray = rg * 32 + warp * 8 + p * 4 + r_i;
            const float4 r4 = __ldg(reinterpret_cast<const float4*>(rays) + ray);
            const float rsx = r4.x * c - r4.y * s;
            const float rsy = r4.x * s + r4.y * c;
            const float dx  = (r4.z * c - r4.w * s) - rsx;
            const float dy  = (r4.z * s + r4.w * c) - rsy;
            const float t0  = (float)(th * 128 + t_i) + 0.5f;
            const float gx  = rsx + 128.5f + dx * inv_n * t0;
            const float gy  = rsy + 128.5f + dy * inv_n * t0;

            float a0 = 0.f, a1 = 0.f, a2 = 0.f, a3 = 0.f;
            accumulate<16>(gx, gy, dx * inv_n * 8.0f, dy * inv_n * 8.0f,
                           a0, a1, a2, a3);

            a0 += __shfl_xor_sync(0xFFFFFFFFu, a0, 4);
            a0 += __shfl_xor_sync(0xFFFFFFFFu, a0, 8);
            a0 += __shfl_xor_sync(0xFFFFFFFFu, a0, 16);
            a1 += __shfl_xor_sync(0xFFFFFFFFu, a1, 4);
            a1 += __shfl_xor_sync(0xFFFFFFFFu, a1, 8);
            a1 += __shfl_xor_sync(0xFFFFFFFFu, a1, 16);
            a2 += __shfl_xor_sync(0xFFFFFFFFu, a2, 4);
            a2 += __shfl_xor_sync(0xFFFFFFFFu, a2, 8);
            a2 += __shfl_xor_sync(0xFFFFFFFFu, a2, 16);
            a3 += __shfl_xor_sync(0xFFFFFFFFu, a3, 4);
            a3 += __shfl_xor_sync(0xFFFFFFFFu, a3, 8);
            a3 += __shfl_xor_sync(0xFFFFFFFFu, a3, 16);

            if (t_i == 0) {
                const float step = (r4.w - r4.y) * inv_n;
                const int base = a * RES + ray;
                atomicAdd(out + 0 * NA * RES + base, a0 * step);
                atomicAdd(out + 1 * NA * RES + base, a1 * step);
                atomicAdd(out + 2 * NA * RES + base, a2 * step);
                atomicAdd(out + 3 * NA * RES + base, a3 * step);
            }
        }
    }
}

extern "C" void kernel_launch(void* const* d_in, const int* in_sizes, int n_in,
                              void* d_out, int out_size)
{
    const float* imgs   = (const float*)d_in[0];   // [4,256,256]
    const float* angles = (const float*)d_in[1];   // [180]
    const float* rays   = (const float*)d_in[2];   // [256,4]
    float* out          = (float*)d_out;           // [4,180,256]

    const int prep_threads = (NOUT > NPIX ? NOUT : NPIX);
    prep_kernel<<<(prep_threads + 255) / 256, 256>>>(imgs, out);

    dim3 grid(NA, 8, 2);
    radon_kernel<<<grid, 128>>>(angles, rays, out);
}

// round 10
// speedup vs baseline: 1.0529x; 1.0529x over previous
#include <cuda_runtime.h>
#include <cuda_fp16.h>

#define RES 256
#define NA  180
#define NB  4
#define PW  257            // x0p in [0,256]
#define PH  257            // y0p in [0,256]
#define NPIX (PH*PW)
#define NOUT (NB*NA*RES)

// Corner-packed fp16 images, all 4 batches in 32 bytes per padded pixel.
// Within-batch pair layout (R6, best measured):
//   a.x = h2(b0.v00,b0.v01)  a.y = h2(b0.v10,b0.v11)
//   a.z = h2(b1.v00,b1.v01)  a.w = h2(b1.v10,b1.v11)
//   b.* = same for batches 2,3.
// vXY = img[y0+X][x0+Y], OOB -> 0 (zero border = reference's validity mask).
struct __align__(32) Px { uint4 a, b; };
__device__ Px g_P[NPIX];

__device__ __forceinline__ unsigned pack2(float a, float b) {
    __half2 h = __floats2half2_rn(a, b);
    return *reinterpret_cast<unsigned*>(&h);
}
__device__ __forceinline__ float2 unpack2(unsigned u) {
    __half2 h = *reinterpret_cast<__half2*>(&u);
    return __half22float2(h);
}

// 256-bit global load (sm_100+).
__device__ __forceinline__ void ldg256(const Px* p, uint4& a, uint4& b) {
    asm volatile("ld.global.nc.v8.u32 {%0,%1,%2,%3,%4,%5,%6,%7}, [%8];"
                 : "=r"(a.x), "=r"(a.y), "=r"(a.z), "=r"(a.w),
                   "=r"(b.x), "=r"(b.y), "=r"(b.z), "=r"(b.w)
                 : "l"(p));
}
// Register barrier: ties a load's output regs in place so its consumption
// cannot be scheduled before the barrier point.
__device__ __forceinline__ void regbar(uint4& a, uint4& b) {
    asm volatile("" : "+r"(a.x), "+r"(a.y), "+r"(a.z), "+r"(a.w),
                      "+r"(b.x), "+r"(b.y), "+r"(b.z), "+r"(b.w));
}

// Prep: build corner-packed array AND zero the output (radon adds atomically).
__global__ __launch_bounds__(256) void prep_kernel(const float* __restrict__ imgs,
                                                   float* __restrict__ out)
{
    int idx = blockIdx.x * blockDim.x + threadIdx.x;
    if (idx < NOUT) out[idx] = 0.0f;
    if (idx >= NPIX) return;
    const int xp = idx % PW;
    const int yp = idx / PW;
    const int yt = yp - 1, yb = yp;
    const int xl = xp - 1, xr = xp;

    float v[NB][4];
    #pragma unroll
    for (int b = 0; b < NB; ++b) {
        const float* im = imgs + (size_t)b * RES * RES;
        const bool vt = ((unsigned)yt < RES), vb = ((unsigned)yb < RES);
        const bool vl = ((unsigned)xl < RES), vr = ((unsigned)xr < RES);
        v[b][0] = (vt && vl) ? im[yt * RES + xl] : 0.0f;   // v00
        v[b][1] = (vt && vr) ? im[yt * RES + xr] : 0.0f;   // v01
        v[b][2] = (vb && vl) ? im[yb * RES + xl] : 0.0f;   // v10
        v[b][3] = (vb && vr) ? im[yb * RES + xr] : 0.0f;   // v11
    }
    Px px;
    px.a.x = pack2(v[0][0], v[0][1]);  px.a.y = pack2(v[0][2], v[0][3]);
    px.a.z = pack2(v[1][0], v[1][1]);  px.a.w = pack2(v[1][2], v[1][3]);
    px.b.x = pack2(v[2][0], v[2][1]);  px.b.y = pack2(v[2][2], v[2][3]);
    px.b.z = pack2(v[3][0], v[3][1]);  px.b.w = pack2(v[3][2], v[3][3]);
    g_P[idx] = px;
}

// fp32 bilerp from packed (v00,v01)/(v10,v11) words (R6 path, best measured).
__device__ __forceinline__ void bilerp_acc(unsigned top, unsigned bot,
                                           float wx, float wy, float& acc)
{
    const float2 T = unpack2(top);
    const float2 B = unpack2(bot);
    const float ft = fmaf(wx, T.y - T.x, T.x);
    const float fb = fmaf(wx, B.y - B.x, B.x);
    acc += fmaf(wy, fb - ft, ft);
}

// Block = 128 threads (4 warps). Warp tile: 8 rays x 4 t-phases.
// Grid: (angle, ray_group 0..7, t_half 0..1).
// Each block: 32 rays x 128 t-steps (t = th*128 + 4*i + t4, i in [0,32)).
// Inner loop chunked by 4; all 4 LDG.256 issue before any consume (regbar wall).
__global__ __launch_bounds__(128, 6) void radon_kernel(
    const float* __restrict__ angles,
    const float* __restrict__ rays,
    float* __restrict__ out)
{
    const int tid  = threadIdx.x;
    const int lane = tid & 31;
    const int warp = tid >> 5;        // 0..3
    const int r8   = lane & 7;        // ray within warp tile
    const int t4   = lane >> 3;       // t-phase 0..3
    const int a    = blockIdx.x;      // angle
    const int rg   = blockIdx.y;      // ray group 0..7
    const int th   = blockIdx.z;      // t half 0..1
    const int ray  = rg * 32 + warp * 8 + r8;

    const float4 r4 = __ldg(reinterpret_cast<const float4*>(rays) + ray);
    float s, c;
    sincosf(__ldg(angles + a), &s, &c);

    const float rsx = r4.x * c - r4.y * s;
    const float rsy = r4.x * s + r4.y * c;
    const float dx  = (r4.z * c - r4.w * s) - rsx;
    const float dy  = (r4.z * s + r4.w * c) - rsy;

    const float inv_n = 1.0f / RES;
    const float t0 = (float)(th * 128 + t4) + 0.5f;
    // +128.5 folds image-center offset (127.5) and the +1 padding shift.
    float gx = rsx + 128.5f + dx * inv_n * t0;
    float gy = rsy + 128.5f + dy * inv_n * t0;
    const float sx4 = dx * inv_n * 4.0f;
    const float sy4 = dy * inv_n * 4.0f;

    float acc0 = 0.f, acc1 = 0.f, acc2 = 0.f, acc3 = 0.f;

    for (int i = 0; i < 8; ++i) {
        float wxr[4], wyr[4];
        uint4 qa0, qb0, qa1, qb1, qa2, qb2, qa3, qb3;

        // Addresses for all 4 samples.
        int idxr[4];
        #pragma unroll
        for (int j = 0; j < 4; ++j) {
            const float fx = gx + sx4 * (float)j;
            const float fy = gy + sy4 * (float)j;
            const int x0 = __float2int_rd(fx);
            const int y0 = __float2int_rd(fy);
            wxr[j] = fx - (float)x0;
            wyr[j] = fy - (float)y0;
            idxr[j] = y0 * PW + x0;
        }

        // 4 back-to-back 256-bit loads, then a barrier wall so no consume
        // can be scheduled between them -> MLP = 4.
        ldg256(g_P + idxr[0], qa0, qb0);
        ldg256(g_P + idxr[1], qa1, qb1);
        ldg256(g_P + idxr[2], qa2, qb2);
        ldg256(g_P + idxr[3], qa3, qb3);
        regbar(qa0, qb0);
        regbar(qa1, qb1);
        regbar(qa2, qb2);

        // Consume.
        bilerp_acc(qa0.x, qa0.y, wxr[0], wyr[0], acc0);
        bilerp_acc(qa0.z, qa0.w, wxr[0], wyr[0], acc1);
        bilerp_acc(qb0.x, qb0.y, wxr[0], wyr[0], acc2);
        bilerp_acc(qb0.z, qb0.w, wxr[0], wyr[0], acc3);

        bilerp_acc(qa1.x, qa1.y, wxr[1], wyr[1], acc0);
        bilerp_acc(qa1.z, qa1.w, wxr[1], wyr[1], acc1);
        bilerp_acc(qb1.x, qb1.y, wxr[1], wyr[1], acc2);
        bilerp_acc(qb1.z, qb1.w, wxr[1], wyr[1], acc3);

        bilerp_acc(qa2.x, qa2.y, wxr[2], wyr[2], acc0);
        bilerp_acc(qa2.z, qa2.w, wxr[2], wyr[2], acc1);
        bilerp_acc(qb2.x, qb2.y, wxr[2], wyr[2], acc2);
        bilerp_acc(qb2.z, qb2.w, wxr[2], wyr[2], acc3);

        bilerp_acc(qa3.x, qa3.y, wxr[3], wyr[3], acc0);
        bilerp_acc(qa3.z, qa3.w, wxr[3], wyr[3], acc1);
        bilerp_acc(qb3.x, qb3.y, wxr[3], wyr[3], acc2);
        bilerp_acc(qb3.z, qb3.w, wxr[3], wyr[3], acc3);

        gx += sx4 * 4.0f;
        gy += sy4 * 4.0f;
    }

    // Reduce the 4 t-phases of each ray (lanes l, l+8, l+16, l+24).
    acc0 += __shfl_xor_sync(0xFFFFFFFFu, acc0, 8);
    acc0 += __shfl_xor_sync(0xFFFFFFFFu, acc0, 16);
    acc1 += __shfl_xor_sync(0xFFFFFFFFu, acc1, 8);
    acc1 += __shfl_xor_sync(0xFFFFFFFFu, acc1, 16);
    acc2 += __shfl_xor_sync(0xFFFFFFFFu, acc2, 8);
    acc2 += __shfl_xor_sync(0xFFFFFFFFu, acc2, 16);
    acc3 += __shfl_xor_sync(0xFFFFFFFFu, acc3, 8);
    acc3 += __shfl_xor_sync(0xFFFFFFFFu, acc3, 16);

    if (t4 == 0) {
        const float step = (r4.w - r4.y) * inv_n;   // L / n_steps
        const int base = a * RES + ray;
        atomicAdd(out + 0 * NA * RES + base, acc0 * step);
        atomicAdd(out + 1 * NA * RES + base, acc1 * step);
        atomicAdd(out + 2 * NA * RES + base, acc2 * step);
        atomicAdd(out + 3 * NA * RES + base, acc3 * step);
    }
}

extern "C" void kernel_launch(void* const* d_in, const int* in_sizes, int n_in,
                              void* d_out, int out_size)
{
    const float* imgs   = (const float*)d_in[0];   // [4,256,256]
    const float* angles = (const float*)d_in[1];   // [180]
    const float* rays   = (const float*)d_in[2];   // [256,4]
    float* out          = (float*)d_out;           // [4,180,256]

    const int prep_threads = (NOUT > NPIX ? NOUT : NPIX);
    prep_kernel<<<(prep_threads + 255) / 256, 256>>>(imgs, out);

    dim3 grid(NA, 8, 2);
    radon_kernel<<<grid, 128>>>(angles, rays, out);
}